// round 15
// baseline (speedup 1.0000x reference)
#include <cuda_runtime.h>
#include <cuda_fp16.h>
#include <math.h>
#include <cstdint>

#define BATCH 8
#define LSEQ  4096
#define DMODEL 256
#define NHEAD 8
#define DHEAD 32
#define MROWS (BATCH*LSEQ)
#define NUM_LAYERS 4
#define QKVN (3*DMODEL)   // 768

// ---------------- helpers ----------------
__device__ __forceinline__ uint32_t smem_u32(const void* p) {
    uint32_t a;
    asm("{ .reg .u64 t; cvta.to.shared.u64 t, %1; cvt.u32.u64 %0, t; }" : "=r"(a) : "l"(p));
    return a;
}
__device__ __forceinline__ void cpa(uint32_t s, const void* g) {
    asm volatile("cp.async.cg.shared.global [%0], [%1], 16;" :: "r"(s), "l"(g));
}
__device__ __forceinline__ void cpa8(uint32_t s, const void* g) {
    asm volatile("cp.async.ca.shared.global [%0], [%1], 8;" :: "r"(s), "l"(g));
}
__device__ __forceinline__ void cpa_commit() { asm volatile("cp.async.commit_group;" ::: "memory"); }
#define CPA_WAIT(n) asm volatile("cp.async.wait_group %0;" :: "n"(n) : "memory")
__device__ __forceinline__ void ldm_x4(uint32_t* r, uint32_t a) {
    asm volatile("ldmatrix.sync.aligned.m8n8.x4.shared.b16 {%0,%1,%2,%3}, [%4];"
        : "=r"(r[0]), "=r"(r[1]), "=r"(r[2]), "=r"(r[3]) : "r"(a));
}
#define MMA(c, a, b0v, b1v) \
    asm volatile("mma.sync.aligned.m16n8k16.row.col.f32.f16.f16.f32 " \
        "{%0,%1,%2,%3}, {%4,%5,%6,%7}, {%8,%9}, {%0,%1,%2,%3};" \
        : "+f"((c)[0]), "+f"((c)[1]), "+f"((c)[2]), "+f"((c)[3]) \
        : "r"((a)[0]), "r"((a)[1]), "r"((a)[2]), "r"((a)[3]), "r"(b0v), "r"(b1v))
__device__ __forceinline__ float warp_sum(float v) {
    #pragma unroll
    for (int o = 16; o > 0; o >>= 1) v += __shfl_xor_sync(0xffffffffu, v, o);
    return v;
}

// ---------------- scratch ----------------
__device__ float g_x[MROWS * DMODEL];
__device__ float g_kv[BATCH * NHEAD * DHEAD * DHEAD];
__device__ float g_ksum[BATCH * NHEAD * DHEAD];
__device__ float g_kvp[BATCH * NHEAD * 8 * (DHEAD * DHEAD + DHEAD)];
__device__ __half g_qkv[MROWS * QKVN];
__device__ __half g_xh[MROWS * DMODEL];
__device__ __half g_msgh[MROWS * DMODEL];
__device__ __half g_lnh[MROWS * DMODEL];
__device__ __half g_h1h[MROWS * 2 * DMODEL];
__device__ __half g_wh[NUM_LAYERS * 10 * DMODEL * DMODEL];
#define WSZ_D (DMODEL * DMODEL)
#define WSZ_L (10 * WSZ_D)
#define OFF_Q 0
#define OFF_K (1 * WSZ_D)
#define OFF_V (2 * WSZ_D)
#define OFF_M (3 * WSZ_D)
#define OFF_1 (4 * WSZ_D)
#define OFF_2 (8 * WSZ_D)

// ---------------- PE + transposes ----------------
__device__ __forceinline__ float pe_val(int c, int l) {
    int i = c >> 2, m = c & 3;
    float pos = (m < 2) ? (float)((l & 63) + 1) : (float)((l >> 6) + 1);
    float dv = expf(-(float)(2 * i) * 0.07195578490697396f);
    float a = pos * dv;
    return (m & 1) ? cosf(a) : sinf(a);
}
__global__ void add_pe_transpose(const float* __restrict__ feats) {
    __shared__ float t[32][33];
    int b = blockIdx.z, c0 = blockIdx.y * 32, l0 = blockIdx.x * 32;
    int tx = threadIdx.x, ty = threadIdx.y;
    #pragma unroll
    for (int i = ty; i < 32; i += 8) {
        int c = c0 + i, l = l0 + tx;
        t[i][tx] = feats[((size_t)b * DMODEL + c) * LSEQ + l] + pe_val(c, l);
    }
    __syncthreads();
    #pragma unroll
    for (int i = ty; i < 32; i += 8) {
        int l = l0 + i, c = c0 + tx;
        float v = t[tx][i];
        size_t o = ((size_t)b * LSEQ + l) * DMODEL + c;
        g_x[o] = v;
        g_xh[o] = __float2half_rn(v);
    }
}
__global__ void transpose_out(float* __restrict__ out) {
    __shared__ float t[32][33];
    int b = blockIdx.z, c0 = blockIdx.y * 32, l0 = blockIdx.x * 32;
    int tx = threadIdx.x, ty = threadIdx.y;
    #pragma unroll
    for (int i = ty; i < 32; i += 8)
        t[i][tx] = g_x[((size_t)b * LSEQ + l0 + i) * DMODEL + c0 + tx];
    __syncthreads();
    #pragma unroll
    for (int i = ty; i < 32; i += 8)
        out[((size_t)b * DMODEL + c0 + i) * LSEQ + l0 + tx] = t[tx][i];
}

// W[K][N] fp32 -> [N][K] fp16
__global__ void prep_weight(const float* __restrict__ W, __half* __restrict__ Th,
                            int K, int N, int wstride, int ostride) {
    __shared__ float t[32][33];
    int L = blockIdx.z;
    const float* Wp = W + (size_t)L * wstride;
    int k0 = blockIdx.y * 32, n0 = blockIdx.x * 32;
    int tx = threadIdx.x, ty = threadIdx.y;
    #pragma unroll
    for (int i = ty; i < 32; i += 8)
        t[i][tx] = Wp[(size_t)(k0 + i) * N + n0 + tx];
    __syncthreads();
    #pragma unroll
    for (int i = ty; i < 32; i += 8) {
        float v = t[tx][i];
        size_t o = (size_t)L * ostride + (size_t)(n0 + i) * K + k0 + tx;
        Th[o] = __float2half_rn(v);
    }
}

// rows are 64B (32 fp16) wide, 4x16B chunks, swizzled
__device__ __forceinline__ uint32_t toff(int row, int c16) {
    return (uint32_t)(row * 64 + ((c16 ^ ((row >> 1) & 3)) << 4));
}

// ---------------- GEMM A: 128x128, BK=32, 2 CTAs/SM (R13 proven) ----------
#define BM 128
#define BN 128
#define BK 32
#define TILEB 8192
#define STG (2 * TILEB)
#define NSTAGE 4
#define GSMEM (NSTAGE * STG)         // 65536

template <int EPI, bool DUALA>
__global__ __launch_bounds__(256, 2) void mmagemm(
    const __half* __restrict__ A, const __half* __restrict__ A2,
    const __half* __restrict__ B,
    __half* __restrict__ Ch, int Ndim, int Kdim)
{
    extern __shared__ char sraw[];
    const uint32_t sbase = smem_u32(sraw);

    const int tid = threadIdx.x;
    const int bm0 = blockIdx.y * BM, bn0 = blockIdx.x * BN;
    const int lane = tid & 31, warp = tid >> 5;
    const int wm = warp >> 2, wn = warp & 3;

    const int lrow = tid >> 2;
    const int lc16 = tid & 3;

    uint32_t aRB[4]; int aK3[4];
    const int khA = lane >> 4;
    #pragma unroll
    for (int mt = 0; mt < 4; mt++) {
        int row = wm * 64 + mt * 16 + (lane & 15);
        aRB[mt] = sbase + row * 64;
        aK3[mt] = (row >> 1) & 3;
    }
    uint32_t bRB[2]; int bK3[2];
    const int khB = (lane >> 3) & 1;
    #pragma unroll
    for (int g = 0; g < 2; g++) {
        int row = wn * 32 + g * 16 + ((lane >> 4) & 1) * 8 + (lane & 7);
        bRB[g] = sbase + TILEB + row * 64;
        bK3[g] = (row >> 1) & 3;
    }

    float acc[4][4][4];
    #pragma unroll
    for (int i = 0; i < 4; i++)
        #pragma unroll
        for (int j = 0; j < 4; j++)
            #pragma unroll
            for (int e = 0; e < 4; e++) acc[i][j][e] = 0.f;

    const int nk = Kdim / BK;

    auto load_stage = [&](int st, int kblk) {
        uint32_t sb = sbase + (uint32_t)st * STG;
        const __half* pA;
        int acol, astr;
        if (DUALA && kblk >= DMODEL) {
            pA = A2; acol = kblk - DMODEL; astr = DMODEL;
        } else {
            pA = A; acol = kblk; astr = DUALA ? DMODEL : Kdim;
        }
        #pragma unroll
        for (int i = 0; i < 2; i++) {
            int row = lrow + i * 64;
            uint32_t so = toff(row, lc16);
            size_t gA = (size_t)(bm0 + row) * astr + acol + lc16 * 8;
            size_t gB = (size_t)(bn0 + row) * Kdim + kblk + lc16 * 8;
            cpa(sb + so, pA + gA);
            cpa(sb + TILEB + so, B + gB);
        }
        cpa_commit();
    };

    load_stage(0, 0);
    load_stage(1, BK);
    load_stage(2, 2 * BK);

    for (int c = 0; c < nk; c++) {
        CPA_WAIT(NSTAGE - 2);
        __syncthreads();
        if (c + 3 < nk) load_stage((c + 3) % NSTAGE, (c + 3) * BK);
        else cpa_commit();

        uint32_t soff = (uint32_t)(c % NSTAGE) * STG;
        #pragma unroll
        for (int s = 0; s < 2; s++) {
            uint32_t a[4][4], bh[2][4];
            #pragma unroll
            for (int mt = 0; mt < 4; mt++)
                ldm_x4(a[mt], aRB[mt] + soff + (uint32_t)(((s * 2 + khA) ^ aK3[mt]) << 4));
            #pragma unroll
            for (int g = 0; g < 2; g++)
                ldm_x4(bh[g], bRB[g] + soff + (uint32_t)(((s * 2 + khB) ^ bK3[g]) << 4));
            #pragma unroll
            for (int mt = 0; mt < 4; mt++)
                #pragma unroll
                for (int nt = 0; nt < 4; nt++)
                    MMA(acc[mt][nt], a[mt], bh[nt >> 1][(nt & 1) * 2], bh[nt >> 1][(nt & 1) * 2 + 1]);
        }
    }

    const bool qkv_act = (EPI == 3) && (bn0 < 2 * DMODEL);
    #pragma unroll
    for (int mt = 0; mt < 4; mt++) {
        #pragma unroll
        for (int nt = 0; nt < 4; nt++) {
            int row = bm0 + wm * 64 + mt * 16 + (lane >> 2);
            int col = bn0 + wn * 32 + nt * 8 + (lane & 3) * 2;
            float* a = acc[mt][nt];
            #pragma unroll
            for (int half = 0; half < 2; half++) {
                int r = row + half * 8;
                float v0 = a[half * 2], v1 = a[half * 2 + 1];
                size_t o = (size_t)r * Ndim + col;
                if (EPI == 3) {
                    if (qkv_act) {
                        v0 = v0 > 0.f ? v0 + 1.f : expf(v0);
                        v1 = v1 > 0.f ? v1 + 1.f : expf(v1);
                    }
                } else {
                    v0 = v0 > 0.f ? v0 : 0.f;
                    v1 = v1 > 0.f ? v1 : 0.f;
                }
                __half2 p;
                p.x = __float2half_rn(v0);
                p.y = __float2half_rn(v1);
                *(__half2*)(Ch + o) = p;
            }
        }
    }
}

// ---------------- GEMM B: 64x256, fused row-LayerNorm epilogue ------------
// 256 thr, 8 warps (1m x 8n), warp tile 64x32, BK=32, 4-stage.
// RES=false: LN -> g_lnh fp16.  RES=true: x += LN -> g_x, g_xh.
#define BM2 64
#define BN2 256
#define ATILE2 4096                   // 64x32 fp16
#define BTILE2 16384                  // 256x32 fp16
#define STG2 (ATILE2 + BTILE2)        // 20480
#define GSMEM2 (4 * STG2)             // 81920 >= 64*264*4=67584 epilogue tile

template <bool RES>
__global__ __launch_bounds__(256, 2) void mmagemm_ln(
    const __half* __restrict__ A, const __half* __restrict__ B,
    const float* __restrict__ gam, const float* __restrict__ bet, int Kdim)
{
    extern __shared__ char sraw[];
    const uint32_t sbase = smem_u32(sraw);

    const int tid = threadIdx.x;
    const int bm0 = blockIdx.y * BM2;
    const int lane = tid & 31, warp = tid >> 5;
    const int wn = warp;                  // 8 n-tiles of 32

    const int lrow = tid >> 2;            // 0..63
    const int lc16 = tid & 3;

    uint32_t aRB[4]; int aK3[4];
    const int khA = lane >> 4;
    #pragma unroll
    for (int mt = 0; mt < 4; mt++) {
        int row = mt * 16 + (lane & 15);
        aRB[mt] = sbase + row * 64;
        aK3[mt] = (row >> 1) & 3;
    }
    uint32_t bRB[2]; int bK3[2];
    const int khB = (lane >> 3) & 1;
    #pragma unroll
    for (int g = 0; g < 2; g++) {
        int row = wn * 32 + g * 16 + ((lane >> 4) & 1) * 8 + (lane & 7);
        bRB[g] = sbase + ATILE2 + row * 64;
        bK3[g] = (row >> 1) & 3;
    }

    float acc[4][4][4];
    #pragma unroll
    for (int i = 0; i < 4; i++)
        #pragma unroll
        for (int j = 0; j < 4; j++)
            #pragma unroll
            for (int e = 0; e < 4; e++) acc[i][j][e] = 0.f;

    const int nk = Kdim / BK;

    auto load_stage = [&](int st, int kblk) {
        uint32_t sb = sbase + (uint32_t)st * STG2;
        {   // A: 64 rows x 4 chunks = 256 txns
            uint32_t so = toff(lrow, lc16);
            size_t gA = (size_t)(bm0 + lrow) * Kdim + kblk + lc16 * 8;
            cpa(sb + so, A + gA);
        }
        #pragma unroll
        for (int i = 0; i < 4; i++) {      // B: 256 rows
            int row = lrow + i * 64;
            uint32_t so = toff(row, lc16);
            size_t gB = (size_t)row * Kdim + kblk + lc16 * 8;
            cpa(sb + ATILE2 + so, B + gB);
        }
        cpa_commit();
    };

    load_stage(0, 0);
    load_stage(1, BK);
    load_stage(2, 2 * BK);

    for (int c = 0; c < nk; c++) {
        CPA_WAIT(2);
        __syncthreads();
        if (c + 3 < nk) load_stage((c + 3) % 4, (c + 3) * BK);
        else cpa_commit();

        uint32_t soff = (uint32_t)(c % 4) * STG2;
        #pragma unroll
        for (int s = 0; s < 2; s++) {
            uint32_t a[4][4], bh[2][4];
            #pragma unroll
            for (int mt = 0; mt < 4; mt++)
                ldm_x4(a[mt], aRB[mt] + soff + (uint32_t)(((s * 2 + khA) ^ aK3[mt]) << 4));
            #pragma unroll
            for (int g = 0; g < 2; g++)
                ldm_x4(bh[g], bRB[g] + soff + (uint32_t)(((s * 2 + khB) ^ bK3[g]) << 4));
            #pragma unroll
            for (int mt = 0; mt < 4; mt++)
                #pragma unroll
                for (int nt = 0; nt < 4; nt++)
                    MMA(acc[mt][nt], a[mt], bh[nt >> 1][(nt & 1) * 2], bh[nt >> 1][(nt & 1) * 2 + 1]);
        }
    }

    // drain all cp.async before reusing smem, then stage fp32 tile + LN
    CPA_WAIT(0);
    __syncthreads();
    float* sC = (float*)sraw;              // [64][264]
    #pragma unroll
    for (int mt = 0; mt < 4; mt++) {
        #pragma unroll
        for (int nt = 0; nt < 4; nt++) {
            int rl = mt * 16 + (lane >> 2);
            int cl = wn * 32 + nt * 8 + (lane & 3) * 2;
            float* a = acc[mt][nt];
            #pragma unroll
            for (int half = 0; half < 2; half++) {
                int r = rl + half * 8;
                sC[r * 264 + cl] = a[half * 2];
                sC[r * 264 + cl + 1] = a[half * 2 + 1];
            }
        }
    }
    __syncthreads();
    // 8 warps x 8 rows
    #pragma unroll
    for (int rr = 0; rr < 8; rr++) {
        int rl = warp * 8 + rr;
        int grow = bm0 + rl;
        float v[8]; float s = 0.f;
        #pragma unroll
        for (int j = 0; j < 8; j++) { v[j] = sC[rl * 264 + lane + 32 * j]; s += v[j]; }
        s = warp_sum(s);
        float mu = s * (1.f / 256.f), s2 = 0.f;
        #pragma unroll
        for (int j = 0; j < 8; j++) { float d = v[j] - mu; s2 += d * d; }
        s2 = warp_sum(s2);
        float rs = rsqrtf(s2 * (1.f / 256.f) + 1e-5f);
        #pragma unroll
        for (int j = 0; j < 8; j++) {
            int cidx = lane + 32 * j;
            float lnv = (v[j] - mu) * rs * gam[cidx] + bet[cidx];
            size_t o = (size_t)grow * DMODEL + cidx;
            if (!RES) {
                g_lnh[o] = __float2half_rn(lnv);
            } else {
                float nx = g_x[o] + lnv;
                g_x[o] = nx;
                g_xh[o] = __float2half_rn(nx);
            }
        }
    }
}

// ---------------- KV reduce phase 1: cp.async 3-stage ring ----------------
#define KVSTG 2048

__global__ __launch_bounds__(256) void kv_reduce1() {
    __shared__ __half sK[3][32][32], sV[3][32][32];
    int blk = blockIdx.x;
    int sl = blk & 7, nh = blk >> 3;
    int n = nh >> 3, h = nh & 7;
    const __half* Kp = g_qkv + (size_t)n * LSEQ * QKVN + DMODEL + h * DHEAD;
    const __half* Vp = Kp + DMODEL;
    int tid = threadIdx.x;
    int d0 = tid >> 3, v0 = (tid & 7) * 4;
    int lrow = tid >> 3, lc8 = tid & 7;
    uint32_t skb = smem_u32(&sK[0][0][0]);
    uint32_t svb = smem_u32(&sV[0][0][0]);
    uint32_t so = (uint32_t)(lrow * 64 + lc8 * 8);
    int lbeg = sl * 512;

    auto issue = [&](int t) {
        uint32_t st = (uint32_t)(t % 3) * KVSTG;
        size_t ro = (size_t)(lbeg + t * 32 + lrow) * QKVN + lc8 * 4;
        cpa8(skb + st + so, Kp + ro);
        cpa8(svb + st + so, Vp + ro);
        cpa_commit();
    };

    issue(0); issue(1);

    float a0 = 0, a1 = 0, a2 = 0, a3 = 0, ks = 0;
    for (int t = 0; t < 16; t++) {
        CPA_WAIT(1);
        __syncthreads();
        if (t + 2 < 16) issue(t + 2);
        else cpa_commit();
        int st = t % 3;
        #pragma unroll
        for (int r = 0; r < 32; r++) {
            float kd = __half2float(sK[st][r][d0]);
            float2 va = __half22float2(*(__half2*)&sV[st][r][v0]);
            float2 vb = __half22float2(*(__half2*)&sV[st][r][v0 + 2]);
            a0 += kd * va.x;
            a1 += kd * va.y;
            a2 += kd * vb.x;
            a3 += kd * vb.y;
            if ((tid & 7) == 0) ks += kd;
        }
    }
    float* p = g_kvp + (size_t)blk * (DHEAD * DHEAD + DHEAD);
    float* kv = p + d0 * DHEAD + v0;
    kv[0] = a0; kv[1] = a1; kv[2] = a2; kv[3] = a3;
    if ((tid & 7) == 0) p[DHEAD * DHEAD + d0] = ks;
}

__global__ __launch_bounds__(256) void kv_reduce2() {
    int nh = blockIdx.x, tid = threadIdx.x;
    const float* base = g_kvp + (size_t)nh * 8 * (DHEAD * DHEAD + DHEAD);
    #pragma unroll
    for (int ii = 0; ii < 4; ii++) {
        int i = ii * 256 + tid;
        float s = 0;
        #pragma unroll
        for (int p = 0; p < 8; p++) s += base[p * (DHEAD * DHEAD + DHEAD) + i];
        g_kv[(size_t)nh * DHEAD * DHEAD + i] = s;
    }
    if (tid < DHEAD) {
        float s = 0;
        #pragma unroll
        for (int p = 0; p < 8; p++) s += base[p * (DHEAD * DHEAD + DHEAD) + DHEAD * DHEAD + tid];
        g_ksum[(size_t)nh * DHEAD + tid] = s;
    }
}

// ---------------- attention apply: grid (32, 8, 4) ----------------
__global__ __launch_bounds__(256) void attn_apply() {
    int n = blockIdx.y, l0 = blockIdx.x * 128;
    __shared__ float sKV[NHEAD][DHEAD][DHEAD];
    __shared__ float sKs[NHEAD][DHEAD];
    int tid = threadIdx.x;
    const float* kvp = g_kv + (size_t)n * NHEAD * DHEAD * DHEAD;
    for (int i = tid; i < NHEAD * DHEAD * DHEAD; i += 256) ((float*)sKV)[i] = kvp[i];
    for (int i = tid; i < NHEAD * DHEAD; i += 256) ((float*)sKs)[i] = g_ksum[(size_t)n * NHEAD * DHEAD + i];
    __syncthreads();
    int i = blockIdx.z * 256 + tid;
    int h = i >> 7, ll = i & 127;
    const __half* qp = g_qkv + ((size_t)n * LSEQ + l0 + ll) * QKVN + h * DHEAD;
    size_t rowo = ((size_t)n * LSEQ + l0 + ll) * DMODEL + h * DHEAD;
    float q[32];
    #pragma unroll
    for (int d = 0; d < 32; d += 8) {
        uint2 rq = *(const uint2*)(qp + d);
        float2 q01 = __half22float2(*(__half2*)&rq.x);
        float2 q23 = __half22float2(*(__half2*)&rq.y);
        q[d + 0] = q01.x; q[d + 1] = q01.y; q[d + 2] = q23.x; q[d + 3] = q23.y;
        uint2 rq2 = *(const uint2*)(qp + d + 4);
        float2 q45 = __half22float2(*(__half2*)&rq2.x);
        float2 q67 = __half22float2(*(__half2*)&rq2.y);
        q[d + 4] = q45.x; q[d + 5] = q45.y; q[d + 6] = q67.x; q[d + 7] = q67.y;
    }
    float zdot = 0.f;
    #pragma unroll
    for (int d = 0; d < 32; d++) zdot += q[d] * sKs[h][d];
    float z = 1.f / (zdot + 1e-6f);
    #pragma unroll
    for (int v = 0; v < 32; v += 2) {
        float b0 = 0.f, b1 = 0.f;
        #pragma unroll
        for (int d = 0; d < 32; d++) {
            float qq = q[d];
            b0 += qq * sKV[h][d][v];
            b1 += qq * sKV[h][d][v + 1];
        }
        __half2 ph;
        ph.x = __float2half_rn(b0 * z);
        ph.y = __float2half_rn(b1 * z);
        *(__half2*)(g_msgh + rowo + v) = ph;
    }
}

// ---------------- host ----------------
extern "C" void kernel_launch(void* const* d_in, const int* in_sizes, int n_in,
                              void* d_out, int out_size)
{
    const float* feats = (const float*)d_in[0];
    const float* Wq = (const float*)d_in[1];
    const float* Wk = (const float*)d_in[2];
    const float* Wv = (const float*)d_in[3];
    const float* Wm = (const float*)d_in[4];
    const float* W1 = (const float*)d_in[5];
    const float* W2 = (const float*)d_in[6];
    const float* ln1g = (const float*)d_in[7];
    const float* ln1b = (const float*)d_in[8];
    const float* ln2g = (const float*)d_in[9];
    const float* ln2b = (const float*)d_in[10];

    cudaFuncSetAttribute(mmagemm<2, true>,  cudaFuncAttributeMaxDynamicSharedMemorySize, GSMEM);
    cudaFuncSetAttribute(mmagemm<3, false>, cudaFuncAttributeMaxDynamicSharedMemorySize, GSMEM);
    cudaFuncSetAttribute(mmagemm_ln<false>, cudaFuncAttributeMaxDynamicSharedMemorySize, GSMEM2);
    cudaFuncSetAttribute(mmagemm_ln<true>,  cudaFuncAttributeMaxDynamicSharedMemorySize, GSMEM2);

    __half *pqkv, *pxh, *pmh, *plh, *p1h, *pwh;
    cudaGetSymbolAddress((void**)&pqkv, g_qkv);
    cudaGetSymbolAddress((void**)&pxh, g_xh);
    cudaGetSymbolAddress((void**)&pmh, g_msgh);
    cudaGetSymbolAddress((void**)&plh, g_lnh);
    cudaGetSymbolAddress((void**)&p1h, g_h1h);
    cudaGetSymbolAddress((void**)&pwh, g_wh);

    dim3 tb(32, 8);
    prep_weight<<<dim3(8, 8, NUM_LAYERS), tb>>>(Wq, pwh + OFF_Q, DMODEL, DMODEL, WSZ_D, WSZ_L);
    prep_weight<<<dim3(8, 8, NUM_LAYERS), tb>>>(Wk, pwh + OFF_K, DMODEL, DMODEL, WSZ_D, WSZ_L);
    prep_weight<<<dim3(8, 8, NUM_LAYERS), tb>>>(Wv, pwh + OFF_V, DMODEL, DMODEL, WSZ_D, WSZ_L);
    prep_weight<<<dim3(8, 8, NUM_LAYERS), tb>>>(Wm, pwh + OFF_M, DMODEL, DMODEL, WSZ_D, WSZ_L);
    prep_weight<<<dim3(16, 16, NUM_LAYERS), tb>>>(W1, pwh + OFF_1, 2 * DMODEL, 2 * DMODEL, 4 * WSZ_D, WSZ_L);
    prep_weight<<<dim3(8, 16, NUM_LAYERS), tb>>>(W2, pwh + OFF_2, 2 * DMODEL, DMODEL, 2 * WSZ_D, WSZ_L);

    add_pe_transpose<<<dim3(LSEQ / 32, DMODEL / 32, BATCH), tb>>>(feats);

    dim3 blk(256);
    dim3 grid_qkv(QKVN / BN, MROWS / BM);       // (6, 256)
    dim3 grid_2d(2 * DMODEL / BN, MROWS / BM);  // (4, 256)
    dim3 grid_ln(1, MROWS / BM2);               // (1, 512)

    for (int i = 0; i < NUM_LAYERS; i++) {
        size_t wo = (size_t)i * WSZ_L;
        // fused QKV -> fp16 [elu(x@Wq)+1 | elu(x@Wk)+1 | x@Wv]
        mmagemm<3, false><<<grid_qkv, blk, GSMEM>>>(pxh, 0, pwh + wo + OFF_Q, pqkv, QKVN, DMODEL);

        kv_reduce1<<<BATCH * NHEAD * 8, 256>>>();
        kv_reduce2<<<BATCH * NHEAD, 256>>>();
        attn_apply<<<dim3(LSEQ / 128, BATCH, 4), 256>>>();

        // merged = msg @ Wm with fused LN1 -> g_lnh fp16
        mmagemm_ln<false><<<grid_ln, blk, GSMEM2>>>(pmh, pwh + wo + OFF_M,
                                                    ln1g + i * DMODEL, ln1b + i * DMODEL, DMODEL);

        // h1 = relu([x | LN] @ W1) -> fp16
        mmagemm<2, true><<<grid_2d, blk, GSMEM>>>(pxh, plh, pwh + wo + OFF_1, p1h, 2 * DMODEL, 2 * DMODEL);
        // h2 = h1 @ W2 with fused LN2 + residual -> g_x / g_xh
        mmagemm_ln<true><<<grid_ln, blk, GSMEM2>>>(p1h, pwh + wo + OFF_2,
                                                   ln2g + i * DMODEL, ln2b + i * DMODEL, 2 * DMODEL);
    }

    transpose_out<<<dim3(LSEQ / 32, DMODEL / 32, BATCH), tb>>>((float*)d_out);
}

// round 16
// speedup vs baseline: 1.1048x; 1.1048x over previous
#include <cuda_runtime.h>
#include <cuda_fp16.h>
#include <math.h>
#include <cstdint>

#define BATCH 8
#define LSEQ  4096
#define DMODEL 256
#define NHEAD 8
#define DHEAD 32
#define MROWS (BATCH*LSEQ)
#define NUM_LAYERS 4
#define QKVN (3*DMODEL)   // 768

// ---------------- helpers ----------------
__device__ __forceinline__ uint32_t smem_u32(const void* p) {
    uint32_t a;
    asm("{ .reg .u64 t; cvta.to.shared.u64 t, %1; cvt.u32.u64 %0, t; }" : "=r"(a) : "l"(p));
    return a;
}
__device__ __forceinline__ void cpa(uint32_t s, const void* g) {
    asm volatile("cp.async.cg.shared.global [%0], [%1], 16;" :: "r"(s), "l"(g));
}
__device__ __forceinline__ void cpa8(uint32_t s, const void* g) {
    asm volatile("cp.async.ca.shared.global [%0], [%1], 8;" :: "r"(s), "l"(g));
}
__device__ __forceinline__ void cpa_commit() { asm volatile("cp.async.commit_group;" ::: "memory"); }
#define CPA_WAIT(n) asm volatile("cp.async.wait_group %0;" :: "n"(n) : "memory")
__device__ __forceinline__ void ldm_x4(uint32_t* r, uint32_t a) {
    asm volatile("ldmatrix.sync.aligned.m8n8.x4.shared.b16 {%0,%1,%2,%3}, [%4];"
        : "=r"(r[0]), "=r"(r[1]), "=r"(r[2]), "=r"(r[3]) : "r"(a));
}
#define MMA(c, a, b0v, b1v) \
    asm volatile("mma.sync.aligned.m16n8k16.row.col.f32.f16.f16.f32 " \
        "{%0,%1,%2,%3}, {%4,%5,%6,%7}, {%8,%9}, {%0,%1,%2,%3};" \
        : "+f"((c)[0]), "+f"((c)[1]), "+f"((c)[2]), "+f"((c)[3]) \
        : "r"((a)[0]), "r"((a)[1]), "r"((a)[2]), "r"((a)[3]), "r"(b0v), "r"(b1v))
__device__ __forceinline__ float warp_sum(float v) {
    #pragma unroll
    for (int o = 16; o > 0; o >>= 1) v += __shfl_xor_sync(0xffffffffu, v, o);
    return v;
}

// ---------------- scratch ----------------
__device__ float g_x[MROWS * DMODEL];
__device__ float g_kv[BATCH * NHEAD * DHEAD * DHEAD];
__device__ float g_ksum[BATCH * NHEAD * DHEAD];
__device__ float g_kvp[BATCH * NHEAD * 8 * (DHEAD * DHEAD + DHEAD)];
__device__ __half g_qkv[MROWS * QKVN];
__device__ __half g_xh[MROWS * DMODEL];
__device__ __half g_msgh[MROWS * DMODEL];
__device__ __half g_tmph[MROWS * DMODEL];            // fp16 GEMM->LN handoff
__device__ __half g_lnh[MROWS * DMODEL];
__device__ __half g_h1h[MROWS * 2 * DMODEL];
__device__ __half g_wh[NUM_LAYERS * 10 * DMODEL * DMODEL];
#define WSZ_D (DMODEL * DMODEL)
#define WSZ_L (10 * WSZ_D)
#define OFF_Q 0
#define OFF_K (1 * WSZ_D)
#define OFF_V (2 * WSZ_D)
#define OFF_M (3 * WSZ_D)
#define OFF_1 (4 * WSZ_D)
#define OFF_2 (8 * WSZ_D)

// ---------------- PE + transposes ----------------
__device__ __forceinline__ float pe_val(int c, int l) {
    int i = c >> 2, m = c & 3;
    float pos = (m < 2) ? (float)((l & 63) + 1) : (float)((l >> 6) + 1);
    float dv = expf(-(float)(2 * i) * 0.07195578490697396f);
    float a = pos * dv;
    return (m & 1) ? cosf(a) : sinf(a);
}
__global__ void add_pe_transpose(const float* __restrict__ feats) {
    __shared__ float t[32][33];
    int b = blockIdx.z, c0 = blockIdx.y * 32, l0 = blockIdx.x * 32;
    int tx = threadIdx.x, ty = threadIdx.y;
    #pragma unroll
    for (int i = ty; i < 32; i += 8) {
        int c = c0 + i, l = l0 + tx;
        t[i][tx] = feats[((size_t)b * DMODEL + c) * LSEQ + l] + pe_val(c, l);
    }
    __syncthreads();
    #pragma unroll
    for (int i = ty; i < 32; i += 8) {
        int l = l0 + i, c = c0 + tx;
        float v = t[tx][i];
        size_t o = ((size_t)b * LSEQ + l) * DMODEL + c;
        g_x[o] = v;
        g_xh[o] = __float2half_rn(v);
    }
}
__global__ void transpose_out(float* __restrict__ out) {
    __shared__ float t[32][33];
    int b = blockIdx.z, c0 = blockIdx.y * 32, l0 = blockIdx.x * 32;
    int tx = threadIdx.x, ty = threadIdx.y;
    #pragma unroll
    for (int i = ty; i < 32; i += 8)
        t[i][tx] = g_x[((size_t)b * LSEQ + l0 + i) * DMODEL + c0 + tx];
    __syncthreads();
    #pragma unroll
    for (int i = ty; i < 32; i += 8)
        out[((size_t)b * DMODEL + c0 + i) * LSEQ + l0 + tx] = t[tx][i];
}

// ---------------- fused weight prep: one launch for all 6 weights ---------
// flat grid: W1 tiles [0,1024), W2 [1024,1536), Wq/Wk/Wv/Wm 256 each after.
__global__ void prep_all(const float* __restrict__ Wq, const float* __restrict__ Wk,
                         const float* __restrict__ Wv, const float* __restrict__ Wm,
                         const float* __restrict__ W1, const float* __restrict__ W2,
                         __half* __restrict__ out) {
    __shared__ float t[32][33];
    int id = blockIdx.x;
    const float* W; int K, N, wstride; size_t obase; int tile;
    if (id < 1024) {            // W1: [2d][2d], grid 16x16 per layer
        int L = id >> 8; tile = id & 255;
        W = W1 + (size_t)L * 4 * WSZ_D; K = 2 * DMODEL; N = 2 * DMODEL;
        obase = (size_t)L * WSZ_L + OFF_1;
        wstride = 16;           // tiles per row (N/32)
    } else if (id < 1536) {     // W2: [2d][d], grid 8x16 per layer
        int L = (id - 1024) >> 7; tile = (id - 1024) & 127;
        W = W2 + (size_t)L * 2 * WSZ_D; K = 2 * DMODEL; N = DMODEL;
        obase = (size_t)L * WSZ_L + OFF_2;
        wstride = 8;
    } else {                    // Wq/Wk/Wv/Wm: [d][d], grid 8x8 per layer
        int r = id - 1536;      // 0..1023
        int w = r >> 8;         // which weight
        int L = (r & 255) >> 6; tile = r & 63;
        const float* ws[4] = {Wq, Wk, Wv, Wm};
        size_t os[4] = {OFF_Q, OFF_K, OFF_V, OFF_M};
        W = ws[w] + (size_t)L * WSZ_D; K = DMODEL; N = DMODEL;
        obase = (size_t)L * WSZ_L + os[w];
        wstride = 8;
    }
    int n0 = (tile % wstride) * 32, k0 = (tile / wstride) * 32;
    int tx = threadIdx.x, ty = threadIdx.y;
    #pragma unroll
    for (int i = ty; i < 32; i += 8)
        t[i][tx] = W[(size_t)(k0 + i) * N + n0 + tx];
    __syncthreads();
    #pragma unroll
    for (int i = ty; i < 32; i += 8) {
        float v = t[tx][i];
        out[obase + (size_t)(n0 + i) * K + k0 + tx] = __float2half_rn(v);
    }
}

// rows are 64B (32 fp16) wide, 4x16B chunks, swizzled
__device__ __forceinline__ uint32_t toff(int row, int c16) {
    return (uint32_t)(row * 64 + ((c16 ^ ((row >> 1) & 3)) << 4));
}

// ---------------- GEMM: 128x128, BK=32, 2 CTAs/SM (R13/R14 proven) --------
// EPI: 0 plain fp16, 2 relu fp16, 3 qkv fp16 (elu+1 if col<512)
#define BM 128
#define BN 128
#define BK 32
#define TILEB 8192
#define STG (2 * TILEB)
#define NSTAGE 4
#define GSMEM (NSTAGE * STG)         // 65536

template <int EPI, bool DUALA>
__global__ __launch_bounds__(256, 2) void mmagemm(
    const __half* __restrict__ A, const __half* __restrict__ A2,
    const __half* __restrict__ B,
    __half* __restrict__ Ch, int Ndim, int Kdim)
{
    extern __shared__ char sraw[];
    const uint32_t sbase = smem_u32(sraw);

    const int tid = threadIdx.x;
    const int bm0 = blockIdx.y * BM, bn0 = blockIdx.x * BN;
    const int lane = tid & 31, warp = tid >> 5;
    const int wm = warp >> 2, wn = warp & 3;

    const int lrow = tid >> 2;
    const int lc16 = tid & 3;

    uint32_t aRB[4]; int aK3[4];
    const int khA = lane >> 4;
    #pragma unroll
    for (int mt = 0; mt < 4; mt++) {
        int row = wm * 64 + mt * 16 + (lane & 15);
        aRB[mt] = sbase + row * 64;
        aK3[mt] = (row >> 1) & 3;
    }
    uint32_t bRB[2]; int bK3[2];
    const int khB = (lane >> 3) & 1;
    #pragma unroll
    for (int g = 0; g < 2; g++) {
        int row = wn * 32 + g * 16 + ((lane >> 4) & 1) * 8 + (lane & 7);
        bRB[g] = sbase + TILEB + row * 64;
        bK3[g] = (row >> 1) & 3;
    }

    float acc[4][4][4];
    #pragma unroll
    for (int i = 0; i < 4; i++)
        #pragma unroll
        for (int j = 0; j < 4; j++)
            #pragma unroll
            for (int e = 0; e < 4; e++) acc[i][j][e] = 0.f;

    const int nk = Kdim / BK;

    auto load_stage = [&](int st, int kblk) {
        uint32_t sb = sbase + (uint32_t)st * STG;
        const __half* pA;
        int acol, astr;
        if (DUALA && kblk >= DMODEL) {
            pA = A2; acol = kblk - DMODEL; astr = DMODEL;
        } else {
            pA = A; acol = kblk; astr = DUALA ? DMODEL : Kdim;
        }
        #pragma unroll
        for (int i = 0; i < 2; i++) {
            int row = lrow + i * 64;
            uint32_t so = toff(row, lc16);
            size_t gA = (size_t)(bm0 + row) * astr + acol + lc16 * 8;
            size_t gB = (size_t)(bn0 + row) * Kdim + kblk + lc16 * 8;
            cpa(sb + so, pA + gA);
            cpa(sb + TILEB + so, B + gB);
        }
        cpa_commit();
    };

    load_stage(0, 0);
    load_stage(1, BK);
    load_stage(2, 2 * BK);

    for (int c = 0; c < nk; c++) {
        CPA_WAIT(NSTAGE - 2);
        __syncthreads();
        if (c + 3 < nk) load_stage((c + 3) % NSTAGE, (c + 3) * BK);
        else cpa_commit();

        uint32_t soff = (uint32_t)(c % NSTAGE) * STG;
        #pragma unroll
        for (int s = 0; s < 2; s++) {
            uint32_t a[4][4], bh[2][4];
            #pragma unroll
            for (int mt = 0; mt < 4; mt++)
                ldm_x4(a[mt], aRB[mt] + soff + (uint32_t)(((s * 2 + khA) ^ aK3[mt]) << 4));
            #pragma unroll
            for (int g = 0; g < 2; g++)
                ldm_x4(bh[g], bRB[g] + soff + (uint32_t)(((s * 2 + khB) ^ bK3[g]) << 4));
            #pragma unroll
            for (int mt = 0; mt < 4; mt++)
                #pragma unroll
                for (int nt = 0; nt < 4; nt++)
                    MMA(acc[mt][nt], a[mt], bh[nt >> 1][(nt & 1) * 2], bh[nt >> 1][(nt & 1) * 2 + 1]);
        }
    }

    const bool qkv_act = (EPI == 3) && (bn0 < 2 * DMODEL);
    #pragma unroll
    for (int mt = 0; mt < 4; mt++) {
        #pragma unroll
        for (int nt = 0; nt < 4; nt++) {
            int row = bm0 + wm * 64 + mt * 16 + (lane >> 2);
            int col = bn0 + wn * 32 + nt * 8 + (lane & 3) * 2;
            float* a = acc[mt][nt];
            #pragma unroll
            for (int half = 0; half < 2; half++) {
                int r = row + half * 8;
                float v0 = a[half * 2], v1 = a[half * 2 + 1];
                size_t o = (size_t)r * Ndim + col;
                if (EPI == 3) {
                    if (qkv_act) {
                        v0 = v0 > 0.f ? v0 + 1.f : expf(v0);
                        v1 = v1 > 0.f ? v1 + 1.f : expf(v1);
                    }
                } else if (EPI == 2) {
                    v0 = v0 > 0.f ? v0 : 0.f;
                    v1 = v1 > 0.f ? v1 : 0.f;
                }
                __half2 p;
                p.x = __float2half_rn(v0);
                p.y = __float2half_rn(v1);
                *(__half2*)(Ch + o) = p;
            }
        }
    }
}

// ---------------- KV reduce phase 1: cp.async 3-stage ring ----------------
#define KVSTG 2048

__global__ __launch_bounds__(256) void kv_reduce1() {
    __shared__ __half sK[3][32][32], sV[3][32][32];
    int blk = blockIdx.x;
    int sl = blk & 7, nh = blk >> 3;
    int n = nh >> 3, h = nh & 7;
    const __half* Kp = g_qkv + (size_t)n * LSEQ * QKVN + DMODEL + h * DHEAD;
    const __half* Vp = Kp + DMODEL;
    int tid = threadIdx.x;
    int d0 = tid >> 3, v0 = (tid & 7) * 4;
    int lrow = tid >> 3, lc8 = tid & 7;
    uint32_t skb = smem_u32(&sK[0][0][0]);
    uint32_t svb = smem_u32(&sV[0][0][0]);
    uint32_t so = (uint32_t)(lrow * 64 + lc8 * 8);
    int lbeg = sl * 512;

    auto issue = [&](int t) {
        uint32_t st = (uint32_t)(t % 3) * KVSTG;
        size_t ro = (size_t)(lbeg + t * 32 + lrow) * QKVN + lc8 * 4;
        cpa8(skb + st + so, Kp + ro);
        cpa8(svb + st + so, Vp + ro);
        cpa_commit();
    };

    issue(0); issue(1);

    float a0 = 0, a1 = 0, a2 = 0, a3 = 0, ks = 0;
    for (int t = 0; t < 16; t++) {
        CPA_WAIT(1);
        __syncthreads();
        if (t + 2 < 16) issue(t + 2);
        else cpa_commit();
        int st = t % 3;
        #pragma unroll
        for (int r = 0; r < 32; r++) {
            float kd = __half2float(sK[st][r][d0]);
            float2 va = __half22float2(*(__half2*)&sV[st][r][v0]);
            float2 vb = __half22float2(*(__half2*)&sV[st][r][v0 + 2]);
            a0 += kd * va.x;
            a1 += kd * va.y;
            a2 += kd * vb.x;
            a3 += kd * vb.y;
            if ((tid & 7) == 0) ks += kd;
        }
    }
    float* p = g_kvp + (size_t)blk * (DHEAD * DHEAD + DHEAD);
    float* kv = p + d0 * DHEAD + v0;
    kv[0] = a0; kv[1] = a1; kv[2] = a2; kv[3] = a3;
    if ((tid & 7) == 0) p[DHEAD * DHEAD + d0] = ks;
}

__global__ __launch_bounds__(256) void kv_reduce2() {
    int nh = blockIdx.x, tid = threadIdx.x;
    const float* base = g_kvp + (size_t)nh * 8 * (DHEAD * DHEAD + DHEAD);
    #pragma unroll
    for (int ii = 0; ii < 4; ii++) {
        int i = ii * 256 + tid;
        float s = 0;
        #pragma unroll
        for (int p = 0; p < 8; p++) s += base[p * (DHEAD * DHEAD + DHEAD) + i];
        g_kv[(size_t)nh * DHEAD * DHEAD + i] = s;
    }
    if (tid < DHEAD) {
        float s = 0;
        #pragma unroll
        for (int p = 0; p < 8; p++) s += base[p * (DHEAD * DHEAD + DHEAD) + DHEAD * DHEAD + tid];
        g_ksum[(size_t)nh * DHEAD + tid] = s;
    }
}

// ---------------- attention apply: grid (32, 8, 4) ----------------
__global__ __launch_bounds__(256) void attn_apply() {
    int n = blockIdx.y, l0 = blockIdx.x * 128;
    __shared__ float sKV[NHEAD][DHEAD][DHEAD];
    __shared__ float sKs[NHEAD][DHEAD];
    int tid = threadIdx.x;
    const float* kvp = g_kv + (size_t)n * NHEAD * DHEAD * DHEAD;
    for (int i = tid; i < NHEAD * DHEAD * DHEAD; i += 256) ((float*)sKV)[i] = kvp[i];
    for (int i = tid; i < NHEAD * DHEAD; i += 256) ((float*)sKs)[i] = g_ksum[(size_t)n * NHEAD * DHEAD + i];
    __syncthreads();
    int i = blockIdx.z * 256 + tid;
    int h = i >> 7, ll = i & 127;
    const __half* qp = g_qkv + ((size_t)n * LSEQ + l0 + ll) * QKVN + h * DHEAD;
    size_t rowo = ((size_t)n * LSEQ + l0 + ll) * DMODEL + h * DHEAD;
    float q[32];
    #pragma unroll
    for (int d = 0; d < 32; d += 8) {
        uint2 rq = *(const uint2*)(qp + d);
        float2 q01 = __half22float2(*(__half2*)&rq.x);
        float2 q23 = __half22float2(*(__half2*)&rq.y);
        q[d + 0] = q01.x; q[d + 1] = q01.y; q[d + 2] = q23.x; q[d + 3] = q23.y;
        uint2 rq2 = *(const uint2*)(qp + d + 4);
        float2 q45 = __half22float2(*(__half2*)&rq2.x);
        float2 q67 = __half22float2(*(__half2*)&rq2.y);
        q[d + 4] = q45.x; q[d + 5] = q45.y; q[d + 6] = q67.x; q[d + 7] = q67.y;
    }
    float zdot = 0.f;
    #pragma unroll
    for (int d = 0; d < 32; d++) zdot += q[d] * sKs[h][d];
    float z = 1.f / (zdot + 1e-6f);
    #pragma unroll
    for (int v = 0; v < 32; v += 2) {
        float b0 = 0.f, b1 = 0.f;
        #pragma unroll
        for (int d = 0; d < 32; d++) {
            float qq = q[d];
            b0 += qq * sKV[h][d][v];
            b1 += qq * sKV[h][d][v + 1];
        }
        __half2 ph;
        ph.x = __float2half_rn(b0 * z);
        ph.y = __float2half_rn(b1 * z);
        *(__half2*)(g_msgh + rowo + v) = ph;
    }
}

// ---------------- LayerNorms (fp16 input) ----------------
__global__ __launch_bounds__(256) void ln1(
    const __half* __restrict__ inp, const float* __restrict__ gam, const float* __restrict__ bet)
{
    int row = blockIdx.x * 8 + (threadIdx.x >> 5);
    int lane = threadIdx.x & 31;
    const __half* ip = inp + (size_t)row * DMODEL;
    float v[8]; float s = 0.f;
    #pragma unroll
    for (int j = 0; j < 8; j++) { v[j] = __half2float(ip[lane + 32 * j]); s += v[j]; }
    s = warp_sum(s);
    float mu = s * (1.f / 256.f), s2 = 0.f;
    #pragma unroll
    for (int j = 0; j < 8; j++) { float d = v[j] - mu; s2 += d * d; }
    s2 = warp_sum(s2);
    float rs = rsqrtf(s2 * (1.f / 256.f) + 1e-5f);
    size_t co = (size_t)row * DMODEL;
    #pragma unroll
    for (int j = 0; j < 8; j++) {
        int c = lane + 32 * j;
        float lnv = (v[j] - mu) * rs * gam[c] + bet[c];
        g_lnh[co + c] = __float2half_rn(lnv);
    }
}
__global__ __launch_bounds__(256) void ln2_res(
    const __half* __restrict__ inp, const float* __restrict__ gam, const float* __restrict__ bet)
{
    int row = blockIdx.x * 8 + (threadIdx.x >> 5);
    int lane = threadIdx.x & 31;
    const __half* ip = inp + (size_t)row * DMODEL;
    float v[8]; float s = 0.f;
    #pragma unroll
    for (int j = 0; j < 8; j++) { v[j] = __half2float(ip[lane + 32 * j]); s += v[j]; }
    s = warp_sum(s);
    float mu = s * (1.f / 256.f), s2 = 0.f;
    #pragma unroll
    for (int j = 0; j < 8; j++) { float d = v[j] - mu; s2 += d * d; }
    s2 = warp_sum(s2);
    float rs = rsqrtf(s2 * (1.f / 256.f) + 1e-5f);
    float* xp = g_x + (size_t)row * DMODEL;
    size_t xo = (size_t)row * DMODEL;
    #pragma unroll
    for (int j = 0; j < 8; j++) {
        int c = lane + 32 * j;
        float nx = xp[c] + (v[j] - mu) * rs * gam[c] + bet[c];
        xp[c] = nx;
        g_xh[xo + c] = __float2half_rn(nx);
    }
}

// ---------------- host ----------------
extern "C" void kernel_launch(void* const* d_in, const int* in_sizes, int n_in,
                              void* d_out, int out_size)
{
    const float* feats = (const float*)d_in[0];
    const float* Wq = (const float*)d_in[1];
    const float* Wk = (const float*)d_in[2];
    const float* Wv = (const float*)d_in[3];
    const float* Wm = (const float*)d_in[4];
    const float* W1 = (const float*)d_in[5];
    const float* W2 = (const float*)d_in[6];
    const float* ln1g = (const float*)d_in[7];
    const float* ln1b = (const float*)d_in[8];
    const float* ln2g = (const float*)d_in[9];
    const float* ln2b = (const float*)d_in[10];

    cudaFuncSetAttribute(mmagemm<0, false>, cudaFuncAttributeMaxDynamicSharedMemorySize, GSMEM);
    cudaFuncSetAttribute(mmagemm<2, true>,  cudaFuncAttributeMaxDynamicSharedMemorySize, GSMEM);
    cudaFuncSetAttribute(mmagemm<3, false>, cudaFuncAttributeMaxDynamicSharedMemorySize, GSMEM);

    float* px;
    __half *pqkv, *pxh, *pmh, *pth, *plh, *p1h, *pwh;
    cudaGetSymbolAddress((void**)&px, g_x);
    cudaGetSymbolAddress((void**)&pqkv, g_qkv);
    cudaGetSymbolAddress((void**)&pxh, g_xh);
    cudaGetSymbolAddress((void**)&pmh, g_msgh);
    cudaGetSymbolAddress((void**)&pth, g_tmph);
    cudaGetSymbolAddress((void**)&plh, g_lnh);
    cudaGetSymbolAddress((void**)&p1h, g_h1h);
    cudaGetSymbolAddress((void**)&pwh, g_wh);

    dim3 tb(32, 8);
    prep_all<<<2560, tb>>>(Wq, Wk, Wv, Wm, W1, W2, pwh);
    add_pe_transpose<<<dim3(LSEQ / 32, DMODEL / 32, BATCH), tb>>>(feats);

    dim3 blk(256);
    dim3 grid_qkv(QKVN / BN, MROWS / BM);       // (6, 256)
    dim3 grid_d(DMODEL / BN, MROWS / BM);       // (2, 256)
    dim3 grid_2d(2 * DMODEL / BN, MROWS / BM);  // (4, 256)

    for (int i = 0; i < NUM_LAYERS; i++) {
        size_t wo = (size_t)i * WSZ_L;
        // fused QKV -> fp16 [elu(x@Wq)+1 | elu(x@Wk)+1 | x@Wv]
        mmagemm<3, false><<<grid_qkv, blk, GSMEM>>>(pxh, 0, pwh + wo + OFF_Q, pqkv, QKVN, DMODEL);

        kv_reduce1<<<BATCH * NHEAD * 8, 256>>>();
        kv_reduce2<<<BATCH * NHEAD, 256>>>();
        attn_apply<<<dim3(LSEQ / 128, BATCH, 4), 256>>>();

        // merged = msg @ Wm -> fp16 g_tmph
        mmagemm<0, false><<<grid_d, blk, GSMEM>>>(pmh, 0, pwh + wo + OFF_M, pth, DMODEL, DMODEL);
        ln1<<<MROWS / 8, 256>>>(pth, ln1g + i * DMODEL, ln1b + i * DMODEL);

        // h1 = relu([x | LN] @ W1) -> fp16; h2 = h1 @ W2 -> fp16 g_tmph
        mmagemm<2, true><<<grid_2d, blk, GSMEM>>>(pxh, plh, pwh + wo + OFF_1, p1h, 2 * DMODEL, 2 * DMODEL);
        mmagemm<0, false><<<grid_d, blk, GSMEM>>>(p1h, 0, pwh + wo + OFF_2, pth, DMODEL, 2 * DMODEL);

        ln2_res<<<MROWS / 8, 256>>>(pth, ln2g + i * DMODEL, ln2b + i * DMODEL);
    }

    transpose_out<<<dim3(LSEQ / 32, DMODEL / 32, BATCH), tb>>>((float*)d_out);
}

// round 17
// speedup vs baseline: 1.2001x; 1.0863x over previous
#include <cuda_runtime.h>
#include <cuda_fp16.h>
#include <math.h>
#include <cstdint>

#define BATCH 8
#define LSEQ  4096
#define DMODEL 256
#define NHEAD 8
#define DHEAD 32
#define MROWS (BATCH*LSEQ)
#define NUM_LAYERS 4
#define QKVN (3*DMODEL)   // 768

// ---------------- helpers ----------------
__device__ __forceinline__ uint32_t smem_u32(const void* p) {
    uint32_t a;
    asm("{ .reg .u64 t; cvta.to.shared.u64 t, %1; cvt.u32.u64 %0, t; }" : "=r"(a) : "l"(p));
    return a;
}
__device__ __forceinline__ void cpa(uint32_t s, const void* g) {
    asm volatile("cp.async.cg.shared.global [%0], [%1], 16;" :: "r"(s), "l"(g));
}
__device__ __forceinline__ void cpa8(uint32_t s, const void* g) {
    asm volatile("cp.async.ca.shared.global [%0], [%1], 8;" :: "r"(s), "l"(g));
}
__device__ __forceinline__ void cpa_commit() { asm volatile("cp.async.commit_group;" ::: "memory"); }
#define CPA_WAIT(n) asm volatile("cp.async.wait_group %0;" :: "n"(n) : "memory")
__device__ __forceinline__ void ldm_x4(uint32_t* r, uint32_t a) {
    asm volatile("ldmatrix.sync.aligned.m8n8.x4.shared.b16 {%0,%1,%2,%3}, [%4];"
        : "=r"(r[0]), "=r"(r[1]), "=r"(r[2]), "=r"(r[3]) : "r"(a));
}
#define MMA(c, a, b0v, b1v) \
    asm volatile("mma.sync.aligned.m16n8k16.row.col.f32.f16.f16.f32 " \
        "{%0,%1,%2,%3}, {%4,%5,%6,%7}, {%8,%9}, {%0,%1,%2,%3};" \
        : "+f"((c)[0]), "+f"((c)[1]), "+f"((c)[2]), "+f"((c)[3]) \
        : "r"((a)[0]), "r"((a)[1]), "r"((a)[2]), "r"((a)[3]), "r"(b0v), "r"(b1v))
__device__ __forceinline__ float warp_sum(float v) {
    #pragma unroll
    for (int o = 16; o > 0; o >>= 1) v += __shfl_xor_sync(0xffffffffu, v, o);
    return v;
}
__device__ __forceinline__ uint32_t packh(__half lo, __half hi) {
    __half2 t = __halves2half2(lo, hi);
    return *(uint32_t*)&t;
}

// ---------------- scratch ----------------
__device__ float g_x[MROWS * DMODEL];
__device__ float g_kv[BATCH * NHEAD * DHEAD * DHEAD];
__device__ float g_ksum[BATCH * NHEAD * DHEAD];
__device__ float g_kvp[BATCH * NHEAD * 8 * (DHEAD * DHEAD + DHEAD)];
__device__ __half g_qkv[MROWS * QKVN];
__device__ __half g_xh[MROWS * DMODEL];
__device__ __half g_msgh[MROWS * DMODEL];
__device__ __half g_tmph[MROWS * DMODEL];
__device__ __half g_lnh[MROWS * DMODEL];
__device__ __half g_h1h[MROWS * 2 * DMODEL];
__device__ __half g_wh[NUM_LAYERS * 10 * DMODEL * DMODEL];
#define WSZ_D (DMODEL * DMODEL)
#define WSZ_L (10 * WSZ_D)
#define OFF_Q 0
#define OFF_K (1 * WSZ_D)
#define OFF_V (2 * WSZ_D)
#define OFF_M (3 * WSZ_D)
#define OFF_1 (4 * WSZ_D)
#define OFF_2 (8 * WSZ_D)

// ---------------- PE + transposes ----------------
__device__ __forceinline__ float pe_val(int c, int l) {
    int i = c >> 2, m = c & 3;
    float pos = (m < 2) ? (float)((l & 63) + 1) : (float)((l >> 6) + 1);
    float dv = expf(-(float)(2 * i) * 0.07195578490697396f);
    float a = pos * dv;
    return (m & 1) ? cosf(a) : sinf(a);
}
__global__ void add_pe_transpose(const float* __restrict__ feats) {
    __shared__ float t[32][33];
    int b = blockIdx.z, c0 = blockIdx.y * 32, l0 = blockIdx.x * 32;
    int tx = threadIdx.x, ty = threadIdx.y;
    #pragma unroll
    for (int i = ty; i < 32; i += 8) {
        int c = c0 + i, l = l0 + tx;
        t[i][tx] = feats[((size_t)b * DMODEL + c) * LSEQ + l] + pe_val(c, l);
    }
    __syncthreads();
    #pragma unroll
    for (int i = ty; i < 32; i += 8) {
        int l = l0 + i, c = c0 + tx;
        float v = t[tx][i];
        size_t o = ((size_t)b * LSEQ + l) * DMODEL + c;
        g_x[o] = v;
        g_xh[o] = __float2half_rn(v);
    }
}
__global__ void transpose_out(float* __restrict__ out) {
    __shared__ float t[32][33];
    int b = blockIdx.z, c0 = blockIdx.y * 32, l0 = blockIdx.x * 32;
    int tx = threadIdx.x, ty = threadIdx.y;
    #pragma unroll
    for (int i = ty; i < 32; i += 8)
        t[i][tx] = g_x[((size_t)b * LSEQ + l0 + i) * DMODEL + c0 + tx];
    __syncthreads();
    #pragma unroll
    for (int i = ty; i < 32; i += 8)
        out[((size_t)b * DMODEL + c0 + i) * LSEQ + l0 + tx] = t[tx][i];
}

// ---------------- fused weight prep ----------------
__global__ void prep_all(const float* __restrict__ Wq, const float* __restrict__ Wk,
                         const float* __restrict__ Wv, const float* __restrict__ Wm,
                         const float* __restrict__ W1, const float* __restrict__ W2,
                         __half* __restrict__ out) {
    __shared__ float t[32][33];
    int id = blockIdx.x;
    const float* W; int K, N, wstride; size_t obase; int tile;
    if (id < 1024) {
        int L = id >> 8; tile = id & 255;
        W = W1 + (size_t)L * 4 * WSZ_D; K = 2 * DMODEL; N = 2 * DMODEL;
        obase = (size_t)L * WSZ_L + OFF_1;
        wstride = 16;
    } else if (id < 1536) {
        int L = (id - 1024) >> 7; tile = (id - 1024) & 127;
        W = W2 + (size_t)L * 2 * WSZ_D; K = 2 * DMODEL; N = DMODEL;
        obase = (size_t)L * WSZ_L + OFF_2;
        wstride = 8;
    } else {
        int r = id - 1536;
        int w = r >> 8;
        int L = (r & 255) >> 6; tile = r & 63;
        const float* ws[4] = {Wq, Wk, Wv, Wm};
        size_t os[4] = {OFF_Q, OFF_K, OFF_V, OFF_M};
        W = ws[w] + (size_t)L * WSZ_D; K = DMODEL; N = DMODEL;
        obase = (size_t)L * WSZ_L + os[w];
        wstride = 8;
    }
    int n0 = (tile % wstride) * 32, k0 = (tile / wstride) * 32;
    int tx = threadIdx.x, ty = threadIdx.y;
    #pragma unroll
    for (int i = ty; i < 32; i += 8)
        t[i][tx] = W[(size_t)(k0 + i) * N + n0 + tx];
    __syncthreads();
    #pragma unroll
    for (int i = ty; i < 32; i += 8) {
        float v = t[tx][i];
        out[obase + (size_t)(n0 + i) * K + k0 + tx] = __float2half_rn(v);
    }
}

// rows are 64B (32 fp16) wide, 4x16B chunks, swizzled
__device__ __forceinline__ uint32_t toff(int row, int c16) {
    return (uint32_t)(row * 64 + ((c16 ^ ((row >> 1) & 3)) << 4));
}

// ---------------- GEMM: 128x128, BK=32, 2 CTAs/SM (R13/R14 proven) --------
#define BM 128
#define BN 128
#define BK 32
#define TILEB 8192
#define STG (2 * TILEB)
#define NSTAGE 4
#define GSMEM (NSTAGE * STG)

template <int EPI, bool DUALA>
__global__ __launch_bounds__(256, 2) void mmagemm(
    const __half* __restrict__ A, const __half* __restrict__ A2,
    const __half* __restrict__ B,
    __half* __restrict__ Ch, int Ndim, int Kdim)
{
    extern __shared__ char sraw[];
    const uint32_t sbase = smem_u32(sraw);

    const int tid = threadIdx.x;
    const int bm0 = blockIdx.y * BM, bn0 = blockIdx.x * BN;
    const int lane = tid & 31, warp = tid >> 5;
    const int wm = warp >> 2, wn = warp & 3;

    const int lrow = tid >> 2;
    const int lc16 = tid & 3;

    uint32_t aRB[4]; int aK3[4];
    const int khA = lane >> 4;
    #pragma unroll
    for (int mt = 0; mt < 4; mt++) {
        int row = wm * 64 + mt * 16 + (lane & 15);
        aRB[mt] = sbase + row * 64;
        aK3[mt] = (row >> 1) & 3;
    }
    uint32_t bRB[2]; int bK3[2];
    const int khB = (lane >> 3) & 1;
    #pragma unroll
    for (int g = 0; g < 2; g++) {
        int row = wn * 32 + g * 16 + ((lane >> 4) & 1) * 8 + (lane & 7);
        bRB[g] = sbase + TILEB + row * 64;
        bK3[g] = (row >> 1) & 3;
    }

    float acc[4][4][4];
    #pragma unroll
    for (int i = 0; i < 4; i++)
        #pragma unroll
        for (int j = 0; j < 4; j++)
            #pragma unroll
            for (int e = 0; e < 4; e++) acc[i][j][e] = 0.f;

    const int nk = Kdim / BK;

    auto load_stage = [&](int st, int kblk) {
        uint32_t sb = sbase + (uint32_t)st * STG;
        const __half* pA;
        int acol, astr;
        if (DUALA && kblk >= DMODEL) {
            pA = A2; acol = kblk - DMODEL; astr = DMODEL;
        } else {
            pA = A; acol = kblk; astr = DUALA ? DMODEL : Kdim;
        }
        #pragma unroll
        for (int i = 0; i < 2; i++) {
            int row = lrow + i * 64;
            uint32_t so = toff(row, lc16);
            size_t gA = (size_t)(bm0 + row) * astr + acol + lc16 * 8;
            size_t gB = (size_t)(bn0 + row) * Kdim + kblk + lc16 * 8;
            cpa(sb + so, pA + gA);
            cpa(sb + TILEB + so, B + gB);
        }
        cpa_commit();
    };

    load_stage(0, 0);
    load_stage(1, BK);
    load_stage(2, 2 * BK);

    for (int c = 0; c < nk; c++) {
        CPA_WAIT(NSTAGE - 2);
        __syncthreads();
        if (c + 3 < nk) load_stage((c + 3) % NSTAGE, (c + 3) * BK);
        else cpa_commit();

        uint32_t soff = (uint32_t)(c % NSTAGE) * STG;
        #pragma unroll
        for (int s = 0; s < 2; s++) {
            uint32_t a[4][4], bh[2][4];
            #pragma unroll
            for (int mt = 0; mt < 4; mt++)
                ldm_x4(a[mt], aRB[mt] + soff + (uint32_t)(((s * 2 + khA) ^ aK3[mt]) << 4));
            #pragma unroll
            for (int g = 0; g < 2; g++)
                ldm_x4(bh[g], bRB[g] + soff + (uint32_t)(((s * 2 + khB) ^ bK3[g]) << 4));
            #pragma unroll
            for (int mt = 0; mt < 4; mt++)
                #pragma unroll
                for (int nt = 0; nt < 4; nt++)
                    MMA(acc[mt][nt], a[mt], bh[nt >> 1][(nt & 1) * 2], bh[nt >> 1][(nt & 1) * 2 + 1]);
        }
    }

    const bool qkv_act = (EPI == 3) && (bn0 < 2 * DMODEL);
    #pragma unroll
    for (int mt = 0; mt < 4; mt++) {
        #pragma unroll
        for (int nt = 0; nt < 4; nt++) {
            int row = bm0 + wm * 64 + mt * 16 + (lane >> 2);
            int col = bn0 + wn * 32 + nt * 8 + (lane & 3) * 2;
            float* a = acc[mt][nt];
            #pragma unroll
            for (int half = 0; half < 2; half++) {
                int r = row + half * 8;
                float v0 = a[half * 2], v1 = a[half * 2 + 1];
                size_t o = (size_t)r * Ndim + col;
                if (EPI == 3) {
                    if (qkv_act) {
                        v0 = v0 > 0.f ? v0 + 1.f : expf(v0);
                        v1 = v1 > 0.f ? v1 + 1.f : expf(v1);
                    }
                } else if (EPI == 2) {
                    v0 = v0 > 0.f ? v0 : 0.f;
                    v1 = v1 > 0.f ? v1 : 0.f;
                }
                __half2 p;
                p.x = __float2half_rn(v0);
                p.y = __float2half_rn(v1);
                *(__half2*)(Ch + o) = p;
            }
        }
    }
}

// ---------------- KV reduce phase 1: tensor-core version ----------------
// Per block (n,h,slice of 512 rows): KV[32,32] += K_tile^T @ V_tile via
// mma.m16n8k16; fragments built with scalar LDS from [l][*] tiles (rows
// padded to 72B). Warp w owns C block (mt = w>>2 16 rows, n8 = w&3).
#define KVROW 72                      // padded row stride (bytes)
#define KVROWH 36                     // in halves
#define KVTILE (32 * KVROW)           // 2304 B
#define KVSTG2 (2 * KVTILE)           // K + V per stage

__global__ __launch_bounds__(256) void kv_reduce1() {
    __shared__ __align__(16) char skv[3 * KVSTG2];
    __shared__ float sred[8][DHEAD];
    int blk = blockIdx.x;
    int sl = blk & 7, nh = blk >> 3;
    int n = nh >> 3, h = nh & 7;
    const __half* Kp = g_qkv + (size_t)n * LSEQ * QKVN + DMODEL + h * DHEAD;
    const __half* Vp = Kp + DMODEL;
    int tid = threadIdx.x;
    int lane = tid & 31, warp = tid >> 5;
    int mt = warp >> 2, ng = warp & 3;
    uint32_t sb = smem_u32(skv);
    int lrow = tid >> 3, lc8 = tid & 7;
    uint32_t so = (uint32_t)(lrow * KVROW + lc8 * 8);
    int lbeg = sl * 512;

    auto issue = [&](int t) {
        uint32_t st = sb + (uint32_t)(t % 3) * KVSTG2;
        size_t ro = (size_t)(lbeg + t * 32 + lrow) * QKVN + lc8 * 4;
        cpa8(st + so, Kp + ro);
        cpa8(st + KVTILE + so, Vp + ro);
        cpa_commit();
    };
    issue(0); issue(1);

    float acc[4] = {0.f, 0.f, 0.f, 0.f};
    float kpart = 0.f;
    const int kd_d = tid & 31, kd_l = tid >> 5;
    const int am = mt * 16 + (lane >> 2);    // A rows am, am+8
    const int kk = (lane & 3) * 2;           // k offset within k16
    const int bn = ng * 8 + (lane >> 2);     // B column

    for (int t = 0; t < 16; t++) {
        CPA_WAIT(1);
        __syncthreads();
        if (t + 2 < 16) issue(t + 2);
        else cpa_commit();
        const __half* Ks = (const __half*)(skv + (t % 3) * KVSTG2);
        const __half* Vs = (const __half*)(skv + (t % 3) * KVSTG2 + KVTILE);
        #pragma unroll
        for (int ks = 0; ks < 2; ks++) {
            int k0 = ks * 16 + kk;
            uint32_t a[4], b0, b1;
            a[0] = packh(Ks[k0 * KVROWH + am],           Ks[(k0 + 1) * KVROWH + am]);
            a[1] = packh(Ks[k0 * KVROWH + am + 8],       Ks[(k0 + 1) * KVROWH + am + 8]);
            a[2] = packh(Ks[(k0 + 8) * KVROWH + am],     Ks[(k0 + 9) * KVROWH + am]);
            a[3] = packh(Ks[(k0 + 8) * KVROWH + am + 8], Ks[(k0 + 9) * KVROWH + am + 8]);
            b0   = packh(Vs[k0 * KVROWH + bn],           Vs[(k0 + 1) * KVROWH + bn]);
            b1   = packh(Vs[(k0 + 8) * KVROWH + bn],     Vs[(k0 + 9) * KVROWH + bn]);
            MMA(acc, a, b0, b1);
        }
        #pragma unroll
        for (int j = 0; j < 4; j++)
            kpart += __half2float(Ks[(kd_l + j * 8) * KVROWH + kd_d]);
    }

    float* p = g_kvp + (size_t)blk * (DHEAD * DHEAD + DHEAD);
    int row = mt * 16 + (lane >> 2);
    int col = ng * 8 + (lane & 3) * 2;
    *(float2*)(p + row * DHEAD + col) = make_float2(acc[0], acc[1]);
    *(float2*)(p + (row + 8) * DHEAD + col) = make_float2(acc[2], acc[3]);
    sred[kd_l][kd_d] = kpart;
    __syncthreads();
    if (tid < DHEAD) {
        float s = 0.f;
        #pragma unroll
        for (int j = 0; j < 8; j++) s += sred[j][tid];
        p[DHEAD * DHEAD + tid] = s;
    }
}

// ---------------- KV reduce phase 2: sum 8 partials ----------------
__global__ __launch_bounds__(256) void kv_reduce2() {
    int nh = blockIdx.x, tid = threadIdx.x;
    const float* base = g_kvp + (size_t)nh * 8 * (DHEAD * DHEAD + DHEAD);
    #pragma unroll
    for (int ii = 0; ii < 4; ii++) {
        int i = ii * 256 + tid;
        float s = 0;
        #pragma unroll
        for (int p = 0; p < 8; p++) s += base[p * (DHEAD * DHEAD + DHEAD) + i];
        g_kv[(size_t)nh * DHEAD * DHEAD + i] = s;
    }
    if (tid < DHEAD) {
        float s = 0;
        #pragma unroll
        for (int p = 0; p < 8; p++) s += base[p * (DHEAD * DHEAD + DHEAD) + DHEAD * DHEAD + tid];
        g_ksum[(size_t)nh * DHEAD + tid] = s;
    }
}

// ---------------- attention apply: grid (32, 8, 4) ----------------
__global__ __launch_bounds__(256) void attn_apply() {
    int n = blockIdx.y, l0 = blockIdx.x * 128;
    __shared__ float sKV[NHEAD][DHEAD][DHEAD];
    __shared__ float sKs[NHEAD][DHEAD];
    int tid = threadIdx.x;
    const float* kvp = g_kv + (size_t)n * NHEAD * DHEAD * DHEAD;
    for (int i = tid; i < NHEAD * DHEAD * DHEAD; i += 256) ((float*)sKV)[i] = kvp[i];
    for (int i = tid; i < NHEAD * DHEAD; i += 256) ((float*)sKs)[i] = g_ksum[(size_t)n * NHEAD * DHEAD + i];
    __syncthreads();
    int i = blockIdx.z * 256 + tid;
    int h = i >> 7, ll = i & 127;
    const __half* qp = g_qkv + ((size_t)n * LSEQ + l0 + ll) * QKVN + h * DHEAD;
    size_t rowo = ((size_t)n * LSEQ + l0 + ll) * DMODEL + h * DHEAD;
    float q[32];
    #pragma unroll
    for (int d = 0; d < 32; d += 8) {
        uint2 rq = *(const uint2*)(qp + d);
        float2 q01 = __half22float2(*(__half2*)&rq.x);
        float2 q23 = __half22float2(*(__half2*)&rq.y);
        q[d + 0] = q01.x; q[d + 1] = q01.y; q[d + 2] = q23.x; q[d + 3] = q23.y;
        uint2 rq2 = *(const uint2*)(qp + d + 4);
        float2 q45 = __half22float2(*(__half2*)&rq2.x);
        float2 q67 = __half22float2(*(__half2*)&rq2.y);
        q[d + 4] = q45.x; q[d + 5] = q45.y; q[d + 6] = q67.x; q[d + 7] = q67.y;
    }
    float zdot = 0.f;
    #pragma unroll
    for (int d = 0; d < 32; d++) zdot += q[d] * sKs[h][d];
    float z = 1.f / (zdot + 1e-6f);
    #pragma unroll
    for (int v = 0; v < 32; v += 2) {
        float b0 = 0.f, b1 = 0.f;
        #pragma unroll
        for (int d = 0; d < 32; d++) {
            float qq = q[d];
            b0 += qq * sKV[h][d][v];
            b1 += qq * sKV[h][d][v + 1];
        }
        __half2 ph;
        ph.x = __float2half_rn(b0 * z);
        ph.y = __float2half_rn(b1 * z);
        *(__half2*)(g_msgh + rowo + v) = ph;
    }
}

// ---------------- LayerNorms (fp16 input) ----------------
__global__ __launch_bounds__(256) void ln1(
    const __half* __restrict__ inp, const float* __restrict__ gam, const float* __restrict__ bet)
{
    int row = blockIdx.x * 8 + (threadIdx.x >> 5);
    int lane = threadIdx.x & 31;
    const __half* ip = inp + (size_t)row * DMODEL;
    float v[8]; float s = 0.f;
    #pragma unroll
    for (int j = 0; j < 8; j++) { v[j] = __half2float(ip[lane + 32 * j]); s += v[j]; }
    s = warp_sum(s);
    float mu = s * (1.f / 256.f), s2 = 0.f;
    #pragma unroll
    for (int j = 0; j < 8; j++) { float d = v[j] - mu; s2 += d * d; }
    s2 = warp_sum(s2);
    float rs = rsqrtf(s2 * (1.f / 256.f) + 1e-5f);
    size_t co = (size_t)row * DMODEL;
    #pragma unroll
    for (int j = 0; j < 8; j++) {
        int c = lane + 32 * j;
        float lnv = (v[j] - mu) * rs * gam[c] + bet[c];
        g_lnh[co + c] = __float2half_rn(lnv);
    }
}
__global__ __launch_bounds__(256) void ln2_res(
    const __half* __restrict__ inp, const float* __restrict__ gam, const float* __restrict__ bet)
{
    int row = blockIdx.x * 8 + (threadIdx.x >> 5);
    int lane = threadIdx.x & 31;
    const __half* ip = inp + (size_t)row * DMODEL;
    float v[8]; float s = 0.f;
    #pragma unroll
    for (int j = 0; j < 8; j++) { v[j] = __half2float(ip[lane + 32 * j]); s += v[j]; }
    s = warp_sum(s);
    float mu = s * (1.f / 256.f), s2 = 0.f;
    #pragma unroll
    for (int j = 0; j < 8; j++) { float d = v[j] - mu; s2 += d * d; }
    s2 = warp_sum(s2);
    float rs = rsqrtf(s2 * (1.f / 256.f) + 1e-5f);
    float* xp = g_x + (size_t)row * DMODEL;
    size_t xo = (size_t)row * DMODEL;
    #pragma unroll
    for (int j = 0; j < 8; j++) {
        int c = lane + 32 * j;
        float nx = xp[c] + (v[j] - mu) * rs * gam[c] + bet[c];
        xp[c] = nx;
        g_xh[xo + c] = __float2half_rn(nx);
    }
}

// ---------------- host ----------------
extern "C" void kernel_launch(void* const* d_in, const int* in_sizes, int n_in,
                              void* d_out, int out_size)
{
    const float* feats = (const float*)d_in[0];
    const float* Wq = (const float*)d_in[1];
    const float* Wk = (const float*)d_in[2];
    const float* Wv = (const float*)d_in[3];
    const float* Wm = (const float*)d_in[4];
    const float* W1 = (const float*)d_in[5];
    const float* W2 = (const float*)d_in[6];
    const float* ln1g = (const float*)d_in[7];
    const float* ln1b = (const float*)d_in[8];
    const float* ln2g = (const float*)d_in[9];
    const float* ln2b = (const float*)d_in[10];

    cudaFuncSetAttribute(mmagemm<0, false>, cudaFuncAttributeMaxDynamicSharedMemorySize, GSMEM);
    cudaFuncSetAttribute(mmagemm<2, true>,  cudaFuncAttributeMaxDynamicSharedMemorySize, GSMEM);
    cudaFuncSetAttribute(mmagemm<3, false>, cudaFuncAttributeMaxDynamicSharedMemorySize, GSMEM);

    float* px;
    __half *pqkv, *pxh, *pmh, *pth, *plh, *p1h, *pwh;
    cudaGetSymbolAddress((void**)&px, g_x);
    cudaGetSymbolAddress((void**)&pqkv, g_qkv);
    cudaGetSymbolAddress((void**)&pxh, g_xh);
    cudaGetSymbolAddress((void**)&pmh, g_msgh);
    cudaGetSymbolAddress((void**)&pth, g_tmph);
    cudaGetSymbolAddress((void**)&plh, g_lnh);
    cudaGetSymbolAddress((void**)&p1h, g_h1h);
    cudaGetSymbolAddress((void**)&pwh, g_wh);

    dim3 tb(32, 8);
    prep_all<<<2560, tb>>>(Wq, Wk, Wv, Wm, W1, W2, pwh);
    add_pe_transpose<<<dim3(LSEQ / 32, DMODEL / 32, BATCH), tb>>>(feats);

    dim3 blk(256);
    dim3 grid_qkv(QKVN / BN, MROWS / BM);       // (6, 256)
    dim3 grid_d(DMODEL / BN, MROWS / BM);       // (2, 256)
    dim3 grid_2d(2 * DMODEL / BN, MROWS / BM);  // (4, 256)

    for (int i = 0; i < NUM_LAYERS; i++) {
        size_t wo = (size_t)i * WSZ_L;
        // fused QKV -> fp16 [elu(x@Wq)+1 | elu(x@Wk)+1 | x@Wv]
        mmagemm<3, false><<<grid_qkv, blk, GSMEM>>>(pxh, 0, pwh + wo + OFF_Q, pqkv, QKVN, DMODEL);

        kv_reduce1<<<BATCH * NHEAD * 8, 256>>>();
        kv_reduce2<<<BATCH * NHEAD, 256>>>();
        attn_apply<<<dim3(LSEQ / 128, BATCH, 4), 256>>>();

        // merged = msg @ Wm -> fp16 g_tmph
        mmagemm<0, false><<<grid_d, blk, GSMEM>>>(pmh, 0, pwh + wo + OFF_M, pth, DMODEL, DMODEL);
        ln1<<<MROWS / 8, 256>>>(pth, ln1g + i * DMODEL, ln1b + i * DMODEL);

        // h1 = relu([x | LN] @ W1) -> fp16; h2 = h1 @ W2 -> fp16 g_tmph
        mmagemm<2, true><<<grid_2d, blk, GSMEM>>>(pxh, plh, pwh + wo + OFF_1, p1h, 2 * DMODEL, 2 * DMODEL);
        mmagemm<0, false><<<grid_d, blk, GSMEM>>>(p1h, 0, pwh + wo + OFF_2, pth, DMODEL, 2 * DMODEL);

        ln2_res<<<MROWS / 8, 256>>>(pth, ln2g + i * DMODEL, ln2b + i * DMODEL);
    }

    transpose_out<<<dim3(LSEQ / 32, DMODEL / 32, BATCH), tb>>>((float*)d_out);
}